// round 3
// baseline (speedup 1.0000x reference)
#include <cuda_runtime.h>
#include <cuda_bf16.h>
#include <cstdint>

// Problem constants (fixed shapes)
#define BB 8192
#define DD 256
#define KK 64

// ---------------- scratch (static device arrays; no allocation) ----------------
__device__ __nv_bfloat16 g_Xbf[BB * DD];          // 4 MB
__device__ __nv_bfloat16 g_Sbf[KK * DD * DD];     // 8.4 MB
__device__ float         g_logits[BB * KK];       // 2 MB
__device__ float         g_contrib[KK * BB];      // 2 MB

// ---------------- helpers ----------------
__device__ __forceinline__ uint32_t smem_to_u32(const void* p) {
    uint32_t a;
    asm("{ .reg .u64 t; cvta.to.shared.u64 t, %1; cvt.u32.u64 %0, t; }" : "=r"(a) : "l"(p));
    return a;
}

__device__ __forceinline__ void cp_async16(uint32_t dst, const void* src) {
    asm volatile("cp.async.cg.shared.global [%0], [%1], 16;" :: "r"(dst), "l"(src));
}
#define CP_COMMIT() asm volatile("cp.async.commit_group;" ::: "memory")
#define CP_WAIT(n)  asm volatile("cp.async.wait_group %0;" :: "n"(n) : "memory")

__device__ __forceinline__ void ldsm_x4(uint32_t& r0, uint32_t& r1, uint32_t& r2, uint32_t& r3,
                                        uint32_t addr) {
    asm volatile("ldmatrix.sync.aligned.m8n8.x4.shared.b16 {%0,%1,%2,%3}, [%4];"
                 : "=r"(r0), "=r"(r1), "=r"(r2), "=r"(r3) : "r"(addr));
}

__device__ __forceinline__ void mma_bf16(float* d, const uint32_t* a, uint32_t b0, uint32_t b1) {
    asm volatile(
        "mma.sync.aligned.m16n8k16.row.col.f32.bf16.bf16.f32 "
        "{%0,%1,%2,%3}, {%4,%5,%6,%7}, {%8,%9}, {%0,%1,%2,%3};"
        : "+f"(d[0]), "+f"(d[1]), "+f"(d[2]), "+f"(d[3])
        : "r"(a[0]), "r"(a[1]), "r"(a[2]), "r"(a[3]), "r"(b0), "r"(b1));
}

// ---------------- kernel 1: fp32 -> bf16 converts ----------------
__global__ void convX_kernel(const float4* __restrict__ src) {
    int i = blockIdx.x * blockDim.x + threadIdx.x;
    if (i < (BB * DD) / 4) {
        float4 v = src[i];
        __nv_bfloat162* dst = reinterpret_cast<__nv_bfloat162*>(g_Xbf);
        dst[2 * i]     = __floats2bfloat162_rn(v.x, v.y);
        dst[2 * i + 1] = __floats2bfloat162_rn(v.z, v.w);
    }
}

__global__ void convS_kernel(const float4* __restrict__ src) {
    int i = blockIdx.x * blockDim.x + threadIdx.x;
    if (i < (KK * DD * DD) / 4) {
        float4 v = src[i];
        __nv_bfloat162* dst = reinterpret_cast<__nv_bfloat162*>(g_Sbf);
        dst[2 * i]     = __floats2bfloat162_rn(v.x, v.y);
        dst[2 * i + 1] = __floats2bfloat162_rn(v.z, v.w);
    }
}

// ---------------- kernel 2: logits = X @ mu (fp32, exact) ----------------
#define LOGITS_SMEM ((128 * 257 + 256 * 64) * 4)
__global__ void logits_kernel(const float* __restrict__ X, const float* __restrict__ mu) {
    extern __shared__ float sm[];
    float* xs  = sm;                // [128][257] padded
    float* mus = sm + 128 * 257;    // [256][64]
    int t = threadIdx.x;
    int b0 = blockIdx.x * 128;

    const float4* xg = reinterpret_cast<const float4*>(X + (size_t)b0 * DD);
    #pragma unroll
    for (int j = 0; j < 32; j++) {
        int i = t + j * 256;
        float4 v = xg[i];
        int r = i >> 6, c = (i & 63) << 2;
        float* p = xs + r * 257 + c;
        p[0] = v.x; p[1] = v.y; p[2] = v.z; p[3] = v.w;
    }
    const float4* mg = reinterpret_cast<const float4*>(mu);
    float4* ms4 = reinterpret_cast<float4*>(mus);
    #pragma unroll
    for (int j = 0; j < 16; j++) ms4[t + j * 256] = mg[t + j * 256];
    __syncthreads();

    int r = t & 127;
    int kh = (t >> 7) * 32;
    float acc[32];
    #pragma unroll
    for (int kk = 0; kk < 32; kk++) acc[kk] = 0.f;
    const float* xr = xs + r * 257;
    for (int d = 0; d < DD; d++) {
        float xv = xr[d];
        const float* mrow = mus + d * 64 + kh;
        #pragma unroll
        for (int kk = 0; kk < 32; kk++) acc[kk] = fmaf(xv, mrow[kk], acc[kk]);
    }
    float* og = g_logits + (size_t)(b0 + r) * KK + kh;
    #pragma unroll
    for (int kk = 0; kk < 32; kk++) og[kk] = acc[kk];
}

// ---------------- kernel 3: main bf16 mma.sync GEMM + loss epilogue ----------------
// grid (64 b-tiles, 64 k), 512 threads (16 warps).
// Y[i,e] = sum_d X[b0+i,d] * Sigma[k,e,d]; xSx[i] = sum_e Y[i,e]*x[i,e]
// Warp tile m32 x n64; Kdim=256 in 4 chunks of 64, double-buffered cp.async.
// smem: A stages 2x16KB, B stages 2x32KB, reduction 128x4 floats.
#define SMA0 0
#define SMA1 16384
#define SMB0 32768
#define SMB1 65536
#define SMRED 98304
#define GEMM_SMEM (98304 + 2048)

__global__ void __launch_bounds__(512, 1)
gemm_loss_kernel(const int* __restrict__ y) {
    extern __shared__ char smem[];
    uint32_t sb = smem_to_u32(smem);
    const uint32_t A_off[2] = {SMA0, SMA1};
    const uint32_t B_off[2] = {SMB0, SMB1};
    float* red = reinterpret_cast<float*>(smem + SMRED);

    int tid = threadIdx.x, wid = tid >> 5, lid = tid & 31;
    int bt = blockIdx.x, k = blockIdx.y;
    int b0 = bt * 128;
    int mg = wid >> 2, ng = wid & 3;   // warp tile: rows mg*32, cols ng*64

    const char* Abase = reinterpret_cast<const char*>(g_Xbf) + (size_t)b0 * 512;
    const char* Bbase = reinterpret_cast<const char*>(g_Sbf) + (size_t)k * 131072;

    // ---- issue chunk 0 loads ----
    {
        #pragma unroll
        for (int j = 0; j < 2; j++) {     // A: 1024 x 16B
            int i = tid + j * 512;
            int row = i >> 3, cb = (i & 7) * 16;
            uint32_t dst = sb + A_off[0] + row * 128 + (cb ^ ((row & 7) << 4));
            cp_async16(dst, Abase + (size_t)row * 512 + cb);
        }
        #pragma unroll
        for (int j = 0; j < 4; j++) {     // B: 2048 x 16B
            int i = tid + j * 512;
            int row = i >> 3, cb = (i & 7) * 16;
            uint32_t dst = sb + B_off[0] + row * 128 + (cb ^ ((row & 7) << 4));
            cp_async16(dst, Bbase + (size_t)row * 512 + cb);
        }
        CP_COMMIT();
    }

    float acc[2][8][4];
    #pragma unroll
    for (int m = 0; m < 2; m++)
        #pragma unroll
        for (int n = 0; n < 8; n++)
            #pragma unroll
            for (int f = 0; f < 4; f++) acc[m][n][f] = 0.f;

    // precomputed lane addressing for ldmatrix (row = l&15, 16B block = l>>4)
    int lrow = lid & 15;
    int lcb16 = (lid >> 4) * 16;

    #pragma unroll
    for (int c = 0; c < 4; c++) {
        int buf = c & 1;
        if (c < 3) {
            int nb = (c + 1) & 1;
            #pragma unroll
            for (int j = 0; j < 2; j++) {
                int i = tid + j * 512;
                int row = i >> 3, cb = (i & 7) * 16;
                uint32_t dst = sb + A_off[nb] + row * 128 + (cb ^ ((row & 7) << 4));
                cp_async16(dst, Abase + (size_t)row * 512 + (c + 1) * 128 + cb);
            }
            #pragma unroll
            for (int j = 0; j < 4; j++) {
                int i = tid + j * 512;
                int row = i >> 3, cb = (i & 7) * 16;
                uint32_t dst = sb + B_off[nb] + row * 128 + (cb ^ ((row & 7) << 4));
                cp_async16(dst, Bbase + (size_t)row * 512 + (c + 1) * 128 + cb);
            }
            CP_COMMIT();
            CP_WAIT(1);
        } else {
            CP_WAIT(0);
        }
        __syncthreads();

        #pragma unroll
        for (int ks = 0; ks < 4; ks++) {
            int kb = ks * 32 + lcb16;        // byte col within 128B chunk row
            // A fragments: 2 m16 tiles
            uint32_t a[2][4];
            #pragma unroll
            for (int m = 0; m < 2; m++) {
                int row = mg * 32 + m * 16 + lrow;
                uint32_t addr = sb + A_off[buf] + row * 128 + (kb ^ ((row & 7) << 4));
                ldsm_x4(a[m][0], a[m][1], a[m][2], a[m][3], addr);
            }
            // B fragments: 4 n16 groups
            uint32_t bf[4][4];
            #pragma unroll
            for (int g = 0; g < 4; g++) {
                int row = ng * 64 + g * 16 + lrow;
                uint32_t addr = sb + B_off[buf] + row * 128 + (kb ^ ((row & 7) << 4));
                ldsm_x4(bf[g][0], bf[g][1], bf[g][2], bf[g][3], addr);
            }
            #pragma unroll
            for (int m = 0; m < 2; m++)
                #pragma unroll
                for (int g = 0; g < 4; g++) {
                    mma_bf16(acc[m][g * 2 + 0], a[m], bf[g][0], bf[g][2]);
                    mma_bf16(acc[m][g * 2 + 1], a[m], bf[g][1], bf[g][3]);
                }
        }
        __syncthreads();
    }

    // ---- epilogue: dot rows of Y with x, reduce ----
    int gq = lid >> 2;           // quad group: row within m16 tile
    int cq = (lid & 3) * 2;      // col pair base
    float rs[2][2];
    rs[0][0] = rs[0][1] = rs[1][0] = rs[1][1] = 0.f;
    #pragma unroll
    for (int m = 0; m < 2; m++) {
        int r0 = b0 + mg * 32 + m * 16 + gq;
        int r1 = r0 + 8;
        const __nv_bfloat162* x0 = reinterpret_cast<const __nv_bfloat162*>(g_Xbf + (size_t)r0 * 256);
        const __nv_bfloat162* x1 = reinterpret_cast<const __nv_bfloat162*>(g_Xbf + (size_t)r1 * 256);
        #pragma unroll
        for (int nt = 0; nt < 8; nt++) {
            int e = ng * 64 + nt * 8 + cq;
            float2 v0 = __bfloat1622float2(x0[e >> 1]);
            float2 v1 = __bfloat1622float2(x1[e >> 1]);
            rs[m][0] = fmaf(acc[m][nt][0], v0.x, fmaf(acc[m][nt][1], v0.y, rs[m][0]));
            rs[m][1] = fmaf(acc[m][nt][2], v1.x, fmaf(acc[m][nt][3], v1.y, rs[m][1]));
        }
    }
    // quad reduce (lanes sharing the same rows: lid&~3 .. +3)
    #pragma unroll
    for (int m = 0; m < 2; m++) {
        #pragma unroll
        for (int h = 0; h < 2; h++) {
            rs[m][h] += __shfl_xor_sync(0xFFFFFFFF, rs[m][h], 1);
            rs[m][h] += __shfl_xor_sync(0xFFFFFFFF, rs[m][h], 2);
        }
    }
    if ((lid & 3) == 0) {
        #pragma unroll
        for (int m = 0; m < 2; m++) {
            int r0 = mg * 32 + m * 16 + gq;
            red[r0 * 4 + ng]       = rs[m][0];
            red[(r0 + 8) * 4 + ng] = rs[m][1];
        }
    }
    __syncthreads();

    if (tid < 128) {
        int row = tid;
        float4 rv = reinterpret_cast<const float4*>(red)[row];
        float xsx = (rv.x + rv.y) + (rv.z + rv.w);
        int b = b0 + row;
        float l = g_logits[(size_t)b * KK + k];
        int yv = y[b];
        float psi = sqrtf(fmaxf(xsx, 0.f) + l * l);
        float bk  = (k <= yv) ? 1.f : 0.f;
        float kap = ((k == yv) ? 1.f : 0.f) - 0.5f * bk;
        float sp  = psi + log1pf(__expf(-psi));     // softplus(psi), psi >= 0
        g_contrib[(size_t)k * BB + b] = l * kap + bk * (0.5f * psi - sp);
    }
}

// ---------------- kernel 4: deterministic reduce over k ----------------
__global__ void reduce_kernel(float* __restrict__ out) {
    int b = blockIdx.x * blockDim.x + threadIdx.x;
    if (b < BB) {
        float s = 0.f;
        #pragma unroll 8
        for (int k = 0; k < KK; k++) s += g_contrib[(size_t)k * BB + b];
        out[b] = -s;
    }
}

// ---------------- launch ----------------
extern "C" void kernel_launch(void* const* d_in, const int* in_sizes, int n_in,
                              void* d_out, int out_size) {
    (void)in_sizes; (void)n_in; (void)out_size;
    const float* features = (const float*)d_in[0];
    const int*   y        = (const int*)d_in[1];
    const float* mu       = (const float*)d_in[2];
    const float* Sigma    = (const float*)d_in[3];
    float* out = (float*)d_out;

    cudaFuncSetAttribute(logits_kernel,    cudaFuncAttributeMaxDynamicSharedMemorySize, LOGITS_SMEM);
    cudaFuncSetAttribute(gemm_loss_kernel, cudaFuncAttributeMaxDynamicSharedMemorySize, GEMM_SMEM);

    convX_kernel<<<(BB * DD / 4 + 255) / 256, 256>>>(reinterpret_cast<const float4*>(features));
    convS_kernel<<<(KK * DD * DD / 4 + 255) / 256, 256>>>(reinterpret_cast<const float4*>(Sigma));
    logits_kernel<<<BB / 128, 256, LOGITS_SMEM>>>(features, mu);
    dim3 grid(BB / 128, KK);
    gemm_loss_kernel<<<grid, 512, GEMM_SMEM>>>(y);
    reduce_kernel<<<BB / 256, 256>>>(out);
}